// round 2
// baseline (speedup 1.0000x reference)
#include <cuda_runtime.h>

// Shapes fixed by the reference
#define BB 16
#define TT 8192
#define CC 512
#define YY 256
#define C4 (CC / 4)      // 128 float4 lanes per frame row

// One fused kernel.
// grid = BB*YY*2 blocks (one per (b, y, channel-half)), block = 64 threads.
// Each block:
//   1. reduces durations[b, 0..y-1] -> span start, picks durations[b, y] -> cnt
//   2. mean-pools its 64 float4 channel lanes over frames [st, st+cnt)
__global__ void __launch_bounds__(64)
pool_fused_kernel(const float* __restrict__ emg,
                  const int*   __restrict__ dur,
                  float*       __restrict__ out) {
    const int bid  = blockIdx.x;
    const int by   = bid >> 1;         // b*YY + y
    const int half = bid & 1;          // which 64-lane channel half
    const int b    = by >> 8;          // YY == 256
    const int y    = by & 255;
    const int tid  = threadIdx.x;      // 0..63

    // ---- span metadata: start = sum_{j<y} dur[b,j], cnt = dur[b,y] ----
    const int4 v = __ldg(reinterpret_cast<const int4*>(dur + b * YY) + tid);
    const int base = tid * 4;
    int s = 0;
    if (base + 0 < y) s += v.x;
    if (base + 1 < y) s += v.y;
    if (base + 2 < y) s += v.z;
    if (base + 3 < y) s += v.w;

    __shared__ int sh[3];              // [0],[1]: per-warp sums, [2]: cnt
    if ((y >> 2) == tid) {
        int c;
        switch (y & 3) {
            case 0:  c = v.x; break;
            case 1:  c = v.y; break;
            case 2:  c = v.z; break;
            default: c = v.w; break;
        }
        sh[2] = c;
    }
    #pragma unroll
    for (int o = 16; o; o >>= 1) s += __shfl_down_sync(0xffffffffu, s, o);
    if ((tid & 31) == 0) sh[tid >> 5] = s;
    __syncthreads();

    const int start_raw = sh[0] + sh[1];
    const int st  = min(start_raw, TT);
    const int en  = min(start_raw + sh[2], TT);
    const int cnt = en - st;

    // ---- mean-pool cnt frames, 64 float4 lanes per block ----
    const int lane = half * 64 + tid;  // 0..127
    const float4* p = reinterpret_cast<const float4*>(emg)
                      + ((size_t)b * TT + st) * C4 + lane;

    float4 a0 = make_float4(0.f, 0.f, 0.f, 0.f);
    float4 a1 = a0, a2 = a0, a3 = a0;

    int t = 0;
    for (; t + 4 <= cnt; t += 4) {
        const float4 v0 = __ldcs(p + 0 * C4);
        const float4 v1 = __ldcs(p + 1 * C4);
        const float4 v2 = __ldcs(p + 2 * C4);
        const float4 v3 = __ldcs(p + 3 * C4);
        a0.x += v0.x; a0.y += v0.y; a0.z += v0.z; a0.w += v0.w;
        a1.x += v1.x; a1.y += v1.y; a1.z += v1.z; a1.w += v1.w;
        a2.x += v2.x; a2.y += v2.y; a2.z += v2.z; a2.w += v2.w;
        a3.x += v3.x; a3.y += v3.y; a3.z += v3.z; a3.w += v3.w;
        p += 4 * C4;
    }
    for (; t < cnt; t++) {
        const float4 vv = __ldcs(p);
        a0.x += vv.x; a0.y += vv.y; a0.z += vv.z; a0.w += vv.w;
        p += C4;
    }

    const float inv = (cnt > 0) ? (1.0f / (float)cnt) : 0.0f;
    float4 r;
    r.x = (a0.x + a1.x + a2.x + a3.x) * inv;
    r.y = (a0.y + a1.y + a2.y + a3.y) * inv;
    r.z = (a0.z + a1.z + a2.z + a3.z) * inv;
    r.w = (a0.w + a1.w + a2.w + a3.w) * inv;

    reinterpret_cast<float4*>(out)[(size_t)by * C4 + lane] = r;
}

extern "C" void kernel_launch(void* const* d_in, const int* in_sizes, int n_in,
                              void* d_out, int out_size) {
    const float* emg = (const float*)d_in[0];
    const int*   dur = (const int*)d_in[1];
    float*       out = (float*)d_out;

    pool_fused_kernel<<<BB * YY * 2, 64>>>(emg, dur, out);
}

// round 3
// speedup vs baseline: 1.0412x; 1.0412x over previous
#include <cuda_runtime.h>

// Shapes fixed by the reference
#define BB 16
#define TT 8192
#define CC 512
#define YY 256
#define C4 (CC / 4)          // 128 float4 lanes per frame row
#define NSPAN (BB * YY)      // 4096
#define GRID_POOL (148 * 8)  // persistent blocks

// Scratch (allocation-free: __device__ globals)
__device__ int g_start[NSPAN];
__device__ int g_count[NSPAN];
__device__ int g_next;

// ---------------------------------------------------------------------------
// Kernel 1: per-batch inclusive scan of durations -> clamped (start, count),
// and reset the work-stealing counter for this launch.
// grid = BB, block = YY (256 threads)
// ---------------------------------------------------------------------------
__global__ void __launch_bounds__(YY) span_prefix_kernel(const int* __restrict__ dur) {
    __shared__ int s[YY];
    const int b = blockIdx.x;
    const int y = threadIdx.x;
    if (b == 0 && y == 0) g_next = GRID_POOL;   // pool blocks start at blockIdx
    const int v = dur[b * YY + y];
    s[y] = v;
    __syncthreads();
    #pragma unroll
    for (int off = 1; off < YY; off <<= 1) {
        int add = (y >= off) ? s[y - off] : 0;
        __syncthreads();
        s[y] += add;
        __syncthreads();
    }
    const int incl = s[y];
    const int excl = incl - v;
    const int st = min(excl, TT);
    const int en = min(incl, TT);
    g_start[b * YY + y] = st;
    g_count[b * YY + y] = en - st;
}

// ---------------------------------------------------------------------------
// Kernel 2: persistent mean-pool with dynamic span scheduling.
// Each block processes whole spans; 128 threads, each owns one float4
// channel lane -> 2048B fully-contiguous read per frame row (good DRAM
// page locality). Work-stealing via atomicAdd removes tail imbalance.
// ---------------------------------------------------------------------------
__global__ void __launch_bounds__(128, 8)
pool_kernel(const float* __restrict__ emg, float* __restrict__ out) {
    __shared__ int sh_next;
    const int lane = threadIdx.x;    // 0..127

    int by = blockIdx.x;
    while (by < NSPAN) {
        const int b   = by >> 8;     // YY == 256
        const int st  = g_start[by];
        const int cnt = g_count[by];

        const float4* p = reinterpret_cast<const float4*>(emg)
                          + ((size_t)b * TT + st) * C4 + lane;

        float4 a0 = make_float4(0.f, 0.f, 0.f, 0.f);
        float4 a1 = a0, a2 = a0, a3 = a0;

        int t = 0;
        for (; t + 4 <= cnt; t += 4) {
            const float4 v0 = p[0 * C4];
            const float4 v1 = p[1 * C4];
            const float4 v2 = p[2 * C4];
            const float4 v3 = p[3 * C4];
            a0.x += v0.x; a0.y += v0.y; a0.z += v0.z; a0.w += v0.w;
            a1.x += v1.x; a1.y += v1.y; a1.z += v1.z; a1.w += v1.w;
            a2.x += v2.x; a2.y += v2.y; a2.z += v2.z; a2.w += v2.w;
            a3.x += v3.x; a3.y += v3.y; a3.z += v3.z; a3.w += v3.w;
            p += 4 * C4;
        }
        for (; t < cnt; t++) {
            const float4 vv = p[0];
            a0.x += vv.x; a0.y += vv.y; a0.z += vv.z; a0.w += vv.w;
            p += C4;
        }

        const float inv = (cnt > 0) ? (1.0f / (float)cnt) : 0.0f;
        float4 r;
        r.x = (a0.x + a1.x + a2.x + a3.x) * inv;
        r.y = (a0.y + a1.y + a2.y + a3.y) * inv;
        r.z = (a0.z + a1.z + a2.z + a3.z) * inv;
        r.w = (a0.w + a1.w + a2.w + a3.w) * inv;

        reinterpret_cast<float4*>(out)[(size_t)by * C4 + lane] = r;

        // grab next span
        if (lane == 0) sh_next = atomicAdd(&g_next, 1);
        __syncthreads();
        by = sh_next;
        __syncthreads();
    }
}

extern "C" void kernel_launch(void* const* d_in, const int* in_sizes, int n_in,
                              void* d_out, int out_size) {
    const float* emg = (const float*)d_in[0];
    const int*   dur = (const int*)d_in[1];
    float*       out = (float*)d_out;

    span_prefix_kernel<<<BB, YY>>>(dur);
    pool_kernel<<<GRID_POOL, 128>>>(emg, out);
}

// round 4
// speedup vs baseline: 1.0548x; 1.0131x over previous
#include <cuda_runtime.h>

// Shapes fixed by the reference
#define BB 16
#define TT 8192
#define CC 512
#define YY 256
#define C4 (CC / 4)          // 128 float4 lanes per frame row
#define NSPAN (BB * YY)      // 4096
#define GRID_POOL (148 * 8)  // persistent blocks

// Work-stealing state (module-static, self-restoring each launch)
__device__ int g_next = GRID_POOL;
__device__ int g_done = 0;

// ---------------------------------------------------------------------------
// Fused persistent kernel.
// Each block steals whole spans (b, y). Per span:
//   1. threads 0..63 reduce durations[b, 0..y-1] -> start; pick dur[b,y] -> cnt
//   2. 128 threads mean-pool: one float4 channel lane each -> fully
//      contiguous 2048B per frame row, unroll x8 streaming loads.
// Last block to finish restores the steal counter (graph-replay safe).
// ---------------------------------------------------------------------------
__global__ void __launch_bounds__(128, 6)
pool_fused_kernel(const float* __restrict__ emg,
                  const int*   __restrict__ dur,
                  float*       __restrict__ out) {
    __shared__ int sh[4];            // [0],[1] warp sums, [2] cnt, [3] next id
    const int tid = threadIdx.x;     // 0..127

    int by = blockIdx.x;
    while (by < NSPAN) {
        const int b = by >> 8;       // YY == 256
        const int y = by & 255;

        // ---- span metadata: start = sum_{j<y} dur[b,j], cnt = dur[b,y] ----
        if (tid < 64) {
            const int4 v = __ldg(reinterpret_cast<const int4*>(dur) + b * 64 + tid);
            const int base = tid * 4;
            int s = 0;
            if (base + 0 < y) s += v.x;
            if (base + 1 < y) s += v.y;
            if (base + 2 < y) s += v.z;
            if (base + 3 < y) s += v.w;
            if ((y >> 2) == tid) {
                int c;
                switch (y & 3) {
                    case 0:  c = v.x; break;
                    case 1:  c = v.y; break;
                    case 2:  c = v.z; break;
                    default: c = v.w; break;
                }
                sh[2] = c;
            }
            #pragma unroll
            for (int o = 16; o; o >>= 1) s += __shfl_down_sync(0xffffffffu, s, o);
            if ((tid & 31) == 0) sh[tid >> 5] = s;
        }
        __syncthreads();

        const int start_raw = sh[0] + sh[1];
        const int st  = min(start_raw, TT);
        const int en  = min(start_raw + sh[2], TT);
        const int cnt = en - st;

        // ---- mean-pool cnt frames ----
        const float4* p = reinterpret_cast<const float4*>(emg)
                          + ((size_t)b * TT + st) * C4 + tid;

        float4 a0 = make_float4(0.f, 0.f, 0.f, 0.f);
        float4 a1 = a0, a2 = a0, a3 = a0;
        float4 a4 = a0, a5 = a0, a6 = a0, a7 = a0;

        int t = 0;
        for (; t + 8 <= cnt; t += 8) {
            const float4 v0 = __ldcs(p + 0 * C4);
            const float4 v1 = __ldcs(p + 1 * C4);
            const float4 v2 = __ldcs(p + 2 * C4);
            const float4 v3 = __ldcs(p + 3 * C4);
            const float4 v4 = __ldcs(p + 4 * C4);
            const float4 v5 = __ldcs(p + 5 * C4);
            const float4 v6 = __ldcs(p + 6 * C4);
            const float4 v7 = __ldcs(p + 7 * C4);
            a0.x += v0.x; a0.y += v0.y; a0.z += v0.z; a0.w += v0.w;
            a1.x += v1.x; a1.y += v1.y; a1.z += v1.z; a1.w += v1.w;
            a2.x += v2.x; a2.y += v2.y; a2.z += v2.z; a2.w += v2.w;
            a3.x += v3.x; a3.y += v3.y; a3.z += v3.z; a3.w += v3.w;
            a4.x += v4.x; a4.y += v4.y; a4.z += v4.z; a4.w += v4.w;
            a5.x += v5.x; a5.y += v5.y; a5.z += v5.z; a5.w += v5.w;
            a6.x += v6.x; a6.y += v6.y; a6.z += v6.z; a6.w += v6.w;
            a7.x += v7.x; a7.y += v7.y; a7.z += v7.z; a7.w += v7.w;
            p += 8 * C4;
        }
        for (; t < cnt; t++) {
            const float4 vv = __ldcs(p);
            a0.x += vv.x; a0.y += vv.y; a0.z += vv.z; a0.w += vv.w;
            p += C4;
        }

        const float inv = (cnt > 0) ? (1.0f / (float)cnt) : 0.0f;
        float4 r;
        r.x = ((a0.x + a1.x) + (a2.x + a3.x) + (a4.x + a5.x) + (a6.x + a7.x)) * inv;
        r.y = ((a0.y + a1.y) + (a2.y + a3.y) + (a4.y + a5.y) + (a6.y + a7.y)) * inv;
        r.z = ((a0.z + a1.z) + (a2.z + a3.z) + (a4.z + a5.z) + (a6.z + a7.z)) * inv;
        r.w = ((a0.w + a1.w) + (a2.w + a3.w) + (a4.w + a5.w) + (a6.w + a7.w)) * inv;

        reinterpret_cast<float4*>(out)[(size_t)by * C4 + tid] = r;

        // ---- steal next span ----
        if (tid == 0) sh[3] = atomicAdd(&g_next, 1);
        __syncthreads();
        by = sh[3];
        __syncthreads();
    }

    // ---- last block restores steal state for the next (graph) launch ----
    if (tid == 0) {
        const int d = atomicAdd(&g_done, 1);
        if (d == GRID_POOL - 1) {
            g_next = GRID_POOL;
            g_done = 0;
            __threadfence();
        }
    }
}

extern "C" void kernel_launch(void* const* d_in, const int* in_sizes, int n_in,
                              void* d_out, int out_size) {
    const float* emg = (const float*)d_in[0];
    const int*   dur = (const int*)d_in[1];
    float*       out = (float*)d_out;

    pool_fused_kernel<<<GRID_POOL, 128>>>(emg, dur, out);
}